// round 15
// baseline (speedup 1.0000x reference)
#include <cuda_runtime.h>
#include <cuda_fp16.h>
#include <cstdint>

// Problem constants
#define BB   128
#define TT   512
#define HH   1024
#define GG   4096
#define OO   64

#define KC   128           // K per chunk
#define KAP  136           // weight tile padded k extent (halfs)
#define BP   136           // activation padded batch extent (halfs)
#define NSTG 3
#define NB   65            // 32 L1 + 32 L2 + 1 y
#define NTHR 288           // 8 compute warps + 1 producer warp

#define WT_HALFS    (128 * KAP)         // 17408 (A tile: 128 m x 136 k)
#define ATILE_BYTES (WT_HALFS * 2)      // 34816
#define BTILE_HALFS (KC * BP)           // 17408
#define BTILE_BYTES (BTILE_HALFS * 2)   // 34816
#define BHALF_BYTES (BTILE_BYTES / 2)   // 17408 (64-row half tile)
#define STAGE_BYTES (ATILE_BYTES + BTILE_BYTES)  // 69632
#define SMEM_BYTES  (NSTG * STAGE_BYTES + 128)   // 209024

#define XT_HALFS (64 * BP)              // 8704 (per-t x tile)
#define GSB      (128 * 132)            // gate staging buffer stride (floats)

// ---------------- scratch ----------------
__device__ __align__(128) __half d_Wp1[32 * 9  * WT_HALFS];   // L1 tiles (nc=9, zero-padded tail)
__device__ __align__(128) __half d_Wp2[32 * 16 * WT_HALFS];   // L2 tiles (nc=16)
__device__ __align__(128) __half d_Wpo[      8 * WT_HALFS];   // y tiles (M padded to 128)
__device__ __align__(128) float  d_bc1[GG];
__device__ __align__(128) float  d_bc2[GG];
__device__ __align__(128) __half d_Xt [TT * XT_HALFS];        // [t][k64][b136]
__device__ __align__(128) __half d_H1t[2 * HH * BP + 64 * BP];// [parity][j][b136] + overrun slack
__device__ __align__(128) __half d_H2t[2 * HH * BP + 64 * BP];
__device__ __align__(128) float  d_C1 [HH * BB];              // c [j][b]
__device__ __align__(128) float  d_C2 [HH * BB];
__device__ unsigned g_bar;

// ---------------- init: convert + transpose + prepack ----------------
__global__ void init_kernel(const float* __restrict__ x,
                            const float* __restrict__ Wih1, const float* __restrict__ Whh1,
                            const float* __restrict__ bih1, const float* __restrict__ bhh1,
                            const float* __restrict__ Wih2, const float* __restrict__ Whh2,
                            const float* __restrict__ bih2, const float* __restrict__ bhh2,
                            const float* __restrict__ Wout)
{
    long tid = (long)blockIdx.x * blockDim.x + threadIdx.x;
    long stride = (long)gridDim.x * blockDim.x;
    if (tid == 0) g_bar = 0u;

    // L1 tiles: [bi][c][mi][kl], m = bi*128+mi = 4j+g, K = [x(64) | h1(1024)] padded to 1152
    for (long idx = tid; idx < (long)32 * 9 * WT_HALFS; idx += stride) {
        int tile = (int)(idx / WT_HALFS), rem = (int)(idx % WT_HALFS);
        int mi = rem / KAP, kl = rem % KAP;
        int bi = tile / 9, c = tile % 9;
        float v = 0.f;
        if (kl < KC) {
            int kg = c * KC + kl;
            int m = bi * 128 + mi, j = m >> 2, g = m & 3;
            int sj = g * HH + j;
            if (kg < 64)        v = Wih1[(long)sj * 64 + kg];
            else if (kg < 1088) v = Whh1[(long)sj * HH + (kg - 64)];
        }
        d_Wp1[idx] = __float2half(v);
    }
    // L2 tiles: K = [h1(1024) | h2(1024)]
    for (long idx = tid; idx < (long)32 * 16 * WT_HALFS; idx += stride) {
        int tile = (int)(idx / WT_HALFS), rem = (int)(idx % WT_HALFS);
        int mi = rem / KAP, kl = rem % KAP;
        int bi = tile / 16, c = tile % 16;
        float v = 0.f;
        if (kl < KC) {
            int kg = c * KC + kl;
            int m = bi * 128 + mi, j = m >> 2, g = m & 3;
            int sj = g * HH + j;
            v = (kg < HH) ? Wih2[(long)sj * HH + kg] : Whh2[(long)sj * HH + (kg - HH)];
        }
        d_Wp2[idx] = __float2half(v);
    }
    // y tiles (rows 64..127 zero)
    for (long idx = tid; idx < (long)8 * WT_HALFS; idx += stride) {
        int c = (int)(idx / WT_HALFS), rem = (int)(idx % WT_HALFS);
        int mi = rem / KAP, kl = rem % KAP;
        float v = 0.f;
        if (kl < KC && mi < OO) v = Wout[(long)mi * HH + c * KC + kl];
        d_Wpo[idx] = __float2half(v);
    }
    // biases (gate-interleaved: row = 4j+g)
    for (long idx = tid; idx < GG; idx += stride) {
        int row = (int)idx, j = row >> 2, g = row & 3;
        int sj = g * HH + j;
        d_bc1[row] = bih1[sj] + bhh1[sj];
        d_bc2[row] = bih2[sj] + bhh2[sj];
    }
    // x transposed: [t][kl][b] padded
    for (long idx = tid; idx < (long)TT * XT_HALFS; idx += stride) {
        int t = (int)(idx / XT_HALFS), rem = (int)(idx % XT_HALFS);
        int kl = rem / BP, b = rem % BP;
        float v = (b < BB) ? x[((long)b * TT + t) * 64 + kl] : 0.f;
        d_Xt[idx] = __float2half(v);
    }
    // zero state (incl. slack)
    for (long idx = tid; idx < (long)2 * HH * BP + 64 * BP; idx += stride) {
        d_H1t[idx] = __float2half(0.f);
        d_H2t[idx] = __float2half(0.f);
    }
    for (long idx = tid; idx < (long)HH * BB; idx += stride) {
        d_C1[idx] = 0.f;
        d_C2[idx] = 0.f;
    }
}

// ---------------- helpers ----------------
__device__ __forceinline__ void mbar_init(uint32_t mbar, uint32_t count) {
    asm volatile("mbarrier.init.shared.b64 [%0], %1;" :: "r"(mbar), "r"(count) : "memory");
}
__device__ __forceinline__ void mbar_expect_tx(uint32_t mbar, uint32_t bytes) {
    asm volatile("mbarrier.arrive.expect_tx.shared.b64 _, [%0], %1;" :: "r"(mbar), "r"(bytes) : "memory");
}
__device__ __forceinline__ void mbar_arrive(uint32_t mbar) {
    asm volatile("mbarrier.arrive.shared.b64 _, [%0];" :: "r"(mbar) : "memory");
}
__device__ __forceinline__ void mbar_wait(uint32_t mbar, uint32_t parity) {
    asm volatile(
        "{\n\t.reg .pred P;\n\t"
        "W_%=:\n\t"
        "mbarrier.try_wait.parity.acquire.cta.shared::cta.b64 P, [%0], %1;\n\t"
        "@!P bra W_%=;\n\t}"
        :: "r"(mbar), "r"(parity) : "memory");
}
__device__ __forceinline__ void bulk_g2s(uint32_t dst, const void* src, uint32_t bytes, uint32_t mbar) {
    asm volatile("cp.async.bulk.shared::cluster.global.mbarrier::complete_tx::bytes [%0], [%1], %2, [%3];"
                 :: "r"(dst), "l"(src), "r"(bytes), "r"(mbar) : "memory");
}
__device__ __forceinline__ void ldsm_x4(uint32_t* r, uint32_t addr) {
    asm volatile("ldmatrix.sync.aligned.m8n8.x4.shared.b16 {%0,%1,%2,%3}, [%4];"
                 : "=r"(r[0]), "=r"(r[1]), "=r"(r[2]), "=r"(r[3]) : "r"(addr));
}
__device__ __forceinline__ void ldsm_x4_t(uint32_t* r, uint32_t addr) {
    asm volatile("ldmatrix.sync.aligned.m8n8.x4.trans.shared.b16 {%0,%1,%2,%3}, [%4];"
                 : "=r"(r[0]), "=r"(r[1]), "=r"(r[2]), "=r"(r[3]) : "r"(addr));
}
__device__ __forceinline__ void mma16816(float* c, const uint32_t* a, uint32_t b0, uint32_t b1) {
    asm volatile(
        "mma.sync.aligned.m16n8k16.row.col.f32.f16.f16.f32 "
        "{%0,%1,%2,%3}, {%4,%5,%6,%7}, {%8,%9}, {%0,%1,%2,%3};\n"
        : "+f"(c[0]), "+f"(c[1]), "+f"(c[2]), "+f"(c[3])
        : "r"(a[0]), "r"(a[1]), "r"(a[2]), "r"(a[3]), "r"(b0), "r"(b1));
}
__device__ __forceinline__ float sigmoidf_(float v) { return 1.f / (1.f + expf(-v)); }

__device__ __forceinline__ void grid_barrier(unsigned target) {
    __threadfence();
    __syncthreads();
    if (threadIdx.x == 0) {
        atomicAdd(&g_bar, 1u);
        while (*(volatile unsigned*)&g_bar < target) { }
    }
    __syncthreads();
    __threadfence();
}

// ---------------- one GEMM tile (D[m=gates 128][n=batch 128]) + epilogue ----------------
// mode 0: L1 gates step t (nc=9, K=[x|h1(t-1)] padded)
// mode 1: L2 gates step s (nc=16, K=[h1(s)|h2(s-1)])
// mode 2: y proj step u   (nc=8,  K=h2(u); M rows 64..127 zero)
__device__ __forceinline__ void do_tile(int mode, int step, int bi, char* smem,
        const float* __restrict__ b_out, float* __restrict__ out,
        int& cslot, unsigned& cc0, unsigned& cc1, unsigned& cc2,
        int& pslot, unsigned& pp0, unsigned& pp1, unsigned& pp2)
{
    const int tid = threadIdx.x;
    const int warp = tid >> 5, lane = tid & 31;
    const uint32_t smem_u32 = (uint32_t)__cvta_generic_to_shared(smem);
    const uint32_t MB_F = smem_u32 + NSTG * STAGE_BYTES;   // full barriers (tx)
    const uint32_t MB_E = MB_F + 32;                       // empty barriers (count 8)

    const int nc = (mode == 0) ? 9 : (mode == 1) ? 16 : 8;
    const int par = step & 1, parq = par ^ 1;
    const __half* Wt = (mode == 0) ? d_Wp1 + (long)bi * 9 * WT_HALFS
                     : (mode == 1) ? d_Wp2 + (long)bi * 16 * WT_HALFS
                                   : d_Wpo;

    // ---------------- producer warp (warp 8) ----------------
    if (warp == 8) {
        if (lane == 0) {
            for (int f = 0; f < nc; f++) {
                if (pp0 >= 1) mbar_wait(MB_E + 8 * pslot, (pp0 - 1) & 1);
                uint32_t st = smem_u32 + pslot * STAGE_BYTES;
                uint32_t bar = MB_F + 8 * pslot;
                mbar_expect_tx(bar, STAGE_BYTES);
                bulk_g2s(st, Wt + (long)f * WT_HALFS, ATILE_BYTES, bar);
                if (mode == 0) {
                    if (f == 0) {
                        bulk_g2s(st + ATILE_BYTES, d_Xt + (long)step * XT_HALFS, BHALF_BYTES, bar);
                        bulk_g2s(st + ATILE_BYTES + BHALF_BYTES,
                                 d_H1t + (long)parq * HH * BP, BHALF_BYTES, bar);
                    } else {
                        bulk_g2s(st + ATILE_BYTES,
                                 d_H1t + (long)parq * HH * BP + ((long)f * KC - 64) * BP,
                                 BTILE_BYTES, bar);
                    }
                } else if (mode == 1) {
                    const __half* act = (f < 8)
                        ? d_H1t + (long)par  * HH * BP + (long)f * KC * BP
                        : d_H2t + (long)parq * HH * BP + (long)(f - 8) * KC * BP;
                    bulk_g2s(st + ATILE_BYTES, act, BTILE_BYTES, bar);
                } else {
                    bulk_g2s(st + ATILE_BYTES,
                             d_H2t + (long)par * HH * BP + (long)f * KC * BP, BTILE_BYTES, bar);
                }
                unsigned t_ = pp0 + 1; pp0 = pp1; pp1 = pp2; pp2 = t_;
                pslot = (pslot == 2) ? 0 : pslot + 1;
            }
        }
    }

    // ---------------- compute warps: 2M x 2N x 2K, warp tile 64x64 ----------------
    const int wk = warp & 1;                          // K half (64 k = 4 kk)
    const int wm = (warp >> 1) & 1, wn = (warp >> 2) & 1;
    const int g = lane >> 2, tg = lane & 3;
    const int mat = lane >> 3, r8 = lane & 7;

    // lane base offsets (halfs within stage)
    const int aoff = (wm * 64 + (mat & 1) * 8 + r8) * KAP + (mat >> 1) * 8 + wk * 64;
    const int boff = (wk * 64 + (mat & 1) * 8 + r8) * BP + wn * 64 + (mat >> 1) * 8;

    float acc[4][8][4];
#pragma unroll
    for (int i = 0; i < 4; i++)
#pragma unroll
        for (int j = 0; j < 8; j++)
#pragma unroll
            for (int k = 0; k < 4; k++) acc[i][j][k] = 0.f;

    if (warp < 8) {
        for (int c = 0; c < nc; c++) {
            mbar_wait(MB_F + 8 * cslot, cc0 & 1);
            uint32_t st = smem_u32 + cslot * STAGE_BYTES;
            uint32_t aB = st + 2 * aoff;
            uint32_t bB = st + ATILE_BYTES + 2 * boff;
#pragma unroll
            for (int kk = 0; kk < 4; kk++) {
                uint32_t fa[4][4], fb[4][4];
#pragma unroll
                for (int mi = 0; mi < 4; mi++)
                    ldsm_x4(fa[mi], aB + 2 * (mi * 16 * KAP + kk * 16));
#pragma unroll
                for (int q = 0; q < 4; q++)
                    ldsm_x4_t(fb[q], bB + 2 * (kk * 16 * BP + 16 * q));
#pragma unroll
                for (int mi = 0; mi < 4; mi++)
#pragma unroll
                    for (int q = 0; q < 4; q++) {
                        mma16816(acc[mi][2 * q],     fa[mi], fb[q][0], fb[q][1]);
                        mma16816(acc[mi][2 * q + 1], fa[mi], fb[q][2], fb[q][3]);
                    }
            }
            if (lane == 0) mbar_arrive(MB_E + 8 * cslot);
            unsigned t_ = cc0 + 1; cc0 = cc1; cc1 = cc2; cc2 = t_;
            cslot = (cslot == 2) ? 0 : cslot + 1;
        }
    }
    __syncthreads();   // all slots drained; safe to alias stage smem

    // ---- stage gates to 2 fp32 buffers [128 m][132] (K-halves separate) ----
    float* Gs = (float*)smem;
    if (warp < 8) {
        float* G = Gs + wk * GSB;
#pragma unroll
        for (int mi = 0; mi < 4; mi++)
#pragma unroll
            for (int nj = 0; nj < 8; nj++) {
                int m0 = wm * 64 + mi * 16 + g;
                int n0 = wn * 64 + nj * 8 + 2 * tg;
                G[m0 * 132 + n0]           = acc[mi][nj][0];
                G[m0 * 132 + n0 + 1]       = acc[mi][nj][1];
                G[(m0 + 8) * 132 + n0]     = acc[mi][nj][2];
                G[(m0 + 8) * 132 + n0 + 1] = acc[mi][nj][3];
            }
    }
    __syncthreads();

    if (mode == 2) {
        if (tid < 256) {
#pragma unroll
            for (int i = 0; i < 32; i++) {
                int e = tid + i * 256;                   // 8192 = 128 b x 64 o
                int b = e >> 6, o = e & 63;
                const float* gq = Gs + o * 132 + b;
                out[((long)b * TT + step) * OO + o] = gq[0] + gq[GSB] + b_out[o];
            }
        }
        return;
    }

    if (tid < 256) {
        const float* bc = (mode == 0) ? d_bc1 : d_bc2;
        float* C        = (mode == 0) ? d_C1 : d_C2;
        __half* Hdst    = ((mode == 0) ? d_H1t : d_H2t) + (long)par * HH * BP;
        const int m0g   = bi * 128;
#pragma unroll
        for (int i = 0; i < 16; i++) {
            int e = tid + i * 256;                       // 4096 = 32 j x 128 b
            int jl = e >> 7, b = e & 127;
            const float* gq = Gs + (4 * jl) * 132 + b;
            float gi = gq[0]   + gq[GSB]       + bc[m0g + 4 * jl + 0];
            float gf = gq[132] + gq[GSB + 132] + bc[m0g + 4 * jl + 1];
            float gg = gq[264] + gq[GSB + 264] + bc[m0g + 4 * jl + 2];
            float go = gq[396] + gq[GSB + 396] + bc[m0g + 4 * jl + 3];
            float iv = sigmoidf_(gi);
            float fv = sigmoidf_(gf);
            float gv = tanhf(gg);
            float ov = sigmoidf_(go);
            int j = bi * 32 + jl;
            float cold = C[j * BB + b];
            float cn = fv * cold + iv * gv;
            C[j * BB + b] = cn;
            Hdst[j * BP + b] = __float2half(ov * tanhf(cn));
        }
    }
}

// ---------------- persistent kernel ----------------
// Phase P(t): L1(t) [bx 0..31] || L2(t-1) [bx 32..63] || y(t-2) [bx 64]
__global__ __launch_bounds__(NTHR, 1)
void lstm_persistent(const float* __restrict__ b_out, float* __restrict__ out)
{
    extern __shared__ char smem[];
    const int tid = threadIdx.x;
    const uint32_t smem_u32 = (uint32_t)__cvta_generic_to_shared(smem);
    const uint32_t MB_F = smem_u32 + NSTG * STAGE_BYTES;
    const uint32_t MB_E = MB_F + 32;

    if (tid == 0) {
#pragma unroll
        for (int s = 0; s < NSTG; s++) {
            mbar_init(MB_F + 8 * s, 1);
            mbar_init(MB_E + 8 * s, 8);
        }
        asm volatile("fence.proxy.async.shared::cta;" ::: "memory");
    }
    __syncthreads();

    const int bx = blockIdx.x;
    unsigned target = 0;
    int cslot = 0, pslot = 0;
    unsigned cc0 = 0, cc1 = 0, cc2 = 0, pp0 = 0, pp1 = 0, pp2 = 0;

    for (int t = 0; t <= TT + 1; t++) {
        if (bx < 32) {
            if (t < TT)
                do_tile(0, t, bx, smem, b_out, out, cslot, cc0, cc1, cc2, pslot, pp0, pp1, pp2);
        } else if (bx < 64) {
            if (t >= 1 && t <= TT)
                do_tile(1, t - 1, bx - 32, smem, b_out, out, cslot, cc0, cc1, cc2, pslot, pp0, pp1, pp2);
        } else {
            if (t >= 2)
                do_tile(2, t - 2, 0, smem, b_out, out, cslot, cc0, cc1, cc2, pslot, pp0, pp1, pp2);
        }
        target += NB;
        grid_barrier(target);
    }
}

// ---------------- launch ----------------
extern "C" void kernel_launch(void* const* d_in, const int* in_sizes, int n_in,
                              void* d_out, int out_size)
{
    const float* x     = (const float*)d_in[0];
    const float* Wih1  = (const float*)d_in[1];
    const float* Whh1  = (const float*)d_in[2];
    const float* bih1  = (const float*)d_in[3];
    const float* bhh1  = (const float*)d_in[4];
    const float* Wih2  = (const float*)d_in[5];
    const float* Whh2  = (const float*)d_in[6];
    const float* bih2  = (const float*)d_in[7];
    const float* bhh2  = (const float*)d_in[8];
    const float* Wout  = (const float*)d_in[9];
    const float* bout  = (const float*)d_in[10];
    float* out = (float*)d_out;

    cudaFuncSetAttribute(lstm_persistent,
                         cudaFuncAttributeMaxDynamicSharedMemorySize, SMEM_BYTES);

    init_kernel<<<2048, 256>>>(x, Wih1, Whh1, bih1, bhh1, Wih2, Whh2, bih2, bhh2, Wout);
    lstm_persistent<<<NB, NTHR, SMEM_BYTES>>>(bout, out);
}